// round 16
// baseline (speedup 1.0000x reference)
#include <cuda_runtime.h>
#include <cuda_bf16.h>
#include <cstdint>

#define L_SEQ 512
#define NB    64
#define HID   1024
#define EMB   512
#define NC    4096   // 4 gates * HID, interleaved col = j*4 + g  (g: 0=i,1=f,2=c,3=o)
#define NCTAS 128    // persistent grid; 1 CTA/SM -> all resident

typedef unsigned long long ull;

// ---------------- device scratch (no allocs allowed) ----------------
__device__ float g_xproj[(size_t)L_SEQ * NB * NC];       // bias + x-part preacts
__device__ float g_Wr[(size_t)(HID + EMB) * NC];         // interleaved fp32 W (embed)
__device__ float g_br[NC];                               // interleaved bias
__device__ __nv_bfloat16 g_WT[2][NC][HID];               // [split][col][k] recurrent W
__device__ __nv_bfloat16 g_hbf[2][2][NB][HID];           // [ping][split][m][k]
__device__ unsigned g_bar;                               // grid barrier counter

// ---------------- packed fp32x2 helpers (embed kernel) ----------------
__device__ __forceinline__ ull pk2(float a, float b) {
    ull r; asm("mov.b64 %0, {%1, %2};" : "=l"(r) : "f"(a), "f"(b)); return r;
}
__device__ __forceinline__ void up2(ull v, float& lo, float& hi) {
    asm("mov.b64 {%0, %1}, %2;" : "=f"(lo), "=f"(hi) : "l"(v));
}
__device__ __forceinline__ void fma2(ull& d, ull a, ull b) {
    asm("fma.rn.f32x2 %0, %1, %2, %0;" : "+l"(d) : "l"(a), "l"(b));
}

// ---------------- misc helpers ----------------
__device__ __forceinline__ uint32_t su32(const void* p) {
    return (uint32_t)__cvta_generic_to_shared(p);
}
__device__ __forceinline__ void cpa16(uint32_t d, const void* g) {
    asm volatile("cp.async.cg.shared.global [%0], [%1], 16;" :: "r"(d), "l"(g));
}
#define CP_COMMIT() asm volatile("cp.async.commit_group;" ::: "memory")
#define CP_WAIT0()  asm volatile("cp.async.wait_group 0;" ::: "memory")

__device__ __forceinline__ void bar_arrive_release(unsigned* p) {
    asm volatile("red.release.gpu.global.add.u32 [%0], %1;" :: "l"(p), "r"(1u)
                 : "memory");
}
__device__ __forceinline__ unsigned ld_acquire(unsigned* p) {
    unsigned v;
    asm volatile("ld.acquire.gpu.global.u32 %0, [%1];" : "=r"(v) : "l"(p) : "memory");
    return v;
}
__device__ __forceinline__ float sigm_f(float v) {
    return __fdividef(1.f, 1.f + __expf(-v));
}
__device__ __forceinline__ float tanh_f(float v) {
    return 1.f - __fdividef(2.f, __expf(2.f * v) + 1.f);
}

// ---------------- tensor-core primitives (portable sm_80 path) ----------------
__device__ __forceinline__ void ldsm_x4(unsigned* r, uint32_t addr) {
    asm volatile("ldmatrix.sync.aligned.m8n8.x4.shared.b16 {%0,%1,%2,%3}, [%4];"
        : "=r"(r[0]), "=r"(r[1]), "=r"(r[2]), "=r"(r[3]) : "r"(addr));
}
__device__ __forceinline__ void mma_bf16(float* d, const unsigned* a,
                                         const unsigned* b) {
    asm volatile(
        "mma.sync.aligned.m16n8k16.row.col.f32.bf16.bf16.f32 "
        "{%0,%1,%2,%3}, {%4,%5,%6,%7}, {%8,%9}, {%0,%1,%2,%3};"
        : "+f"(d[0]), "+f"(d[1]), "+f"(d[2]), "+f"(d[3])
        : "r"(a[0]), "r"(a[1]), "r"(a[2]), "r"(a[3]), "r"(b[0]), "r"(b[1]));
}

// ---------------- init: zero h0 bf16 planes + barrier counter ----------------
__global__ void k_init() {
    int i = blockIdx.x * blockDim.x + threadIdx.x;   // 65536 threads
    unsigned* hb = (unsigned*)g_hbf;                 // 131072 uints total
    hb[i] = 0u; hb[i + 65536] = 0u;
    if (i == 0) g_bar = 0;
}

// ---------------- weight/bias reorg: fp32 interleaved + bf16 hi/lo transposed ----
__global__ void k_reorg(const float* __restrict__ Wi, const float* __restrict__ bi,
                        const float* __restrict__ Wf, const float* __restrict__ bf,
                        const float* __restrict__ Wc, const float* __restrict__ bc,
                        const float* __restrict__ Wo, const float* __restrict__ bo) {
    int idx = blockIdx.x * 256 + threadIdx.x;
    if (idx < (HID + EMB) * HID) {
        int k = idx >> 10, j = idx & (HID - 1);
        size_t s = (size_t)k * HID + j;
        float4 v = make_float4(Wi[s], Wf[s], Wc[s], Wo[s]);
        *(float4*)&g_Wr[(size_t)k * NC + j * 4] = v;
        if (k < HID) {     // recurrent part -> bf16 hi/lo, [col][k]
            float vv[4] = { v.x, v.y, v.z, v.w };
#pragma unroll
            for (int g = 0; g < 4; g++) {
                int col = j * 4 + g;
                __nv_bfloat16 hi = __float2bfloat16(vv[g]);
                __nv_bfloat16 lo = __float2bfloat16(vv[g] - __bfloat162float(hi));
                g_WT[0][col][k] = hi;
                g_WT[1][col][k] = lo;
            }
        }
    }
    if (idx < HID) {
        *(float4*)&g_br[idx * 4] = make_float4(bi[idx], bf[idx], bc[idx], bo[idx]);
    }
}

// ---------------- kernel 1: embedding gather + input projection (unchanged) ------
#define BPAD 20
__global__ __launch_bounds__(256) void k_embed_proj(
    const int* __restrict__ x, const float* __restrict__ emb)
{
    __shared__ float a2[16][132];
    __shared__ float bsh[16 * 16 * BPAD];

    int tid = threadIdx.x;
    int jb  = blockIdx.x * 256;
    int by  = blockIdx.y;

    int arow  = tid & 63;
    int ahalf = tid >> 6;
    long tok  = x[by * 64 + arow];
    const float* erow = emb + (size_t)tok * EMB + ahalf * 4;

    int mg = tid >> 4;
    int cg = tid & 15;

    ull acc[32];
    {
        float4 b0 = *(const float4*)(g_br + jb + cg * 16);
        float4 b1 = *(const float4*)(g_br + jb + cg * 16 + 4);
        float4 b2 = *(const float4*)(g_br + jb + cg * 16 + 8);
        float4 b3 = *(const float4*)(g_br + jb + cg * 16 + 12);
        ull p[8] = { pk2(b0.x, b0.y), pk2(b0.z, b0.w), pk2(b1.x, b1.y), pk2(b1.z, b1.w),
                     pk2(b2.x, b2.y), pk2(b2.z, b2.w), pk2(b3.x, b3.y), pk2(b3.z, b3.w) };
#pragma unroll
        for (int m = 0; m < 4; m++)
#pragma unroll
            for (int q = 0; q < 8; q++) acc[m * 8 + q] = p[q];
    }

    float4 va;
    float4 rb[4];
#define E_LOAD(KB)                                                               \
    va = *(const float4*)(erow + (KB));                                         \
    _Pragma("unroll")                                                            \
    for (int i_ = 0; i_ < 4; i_++) {                                             \
        int f_ = tid + i_ * 256; int r_ = f_ >> 6, q_ = f_ & 63;                 \
        rb[i_] = *(const float4*)&g_Wr[(size_t)(HID + (KB) + r_) * NC + jb + q_ * 4]; \
    }

    E_LOAD(0)

    for (int kb = 0; kb < EMB; kb += 16) {
        __syncthreads();
        {
            int k0 = ahalf * 4;
            *(float2*)&a2[k0 + 0][2 * arow] = make_float2(va.x, va.x);
            *(float2*)&a2[k0 + 1][2 * arow] = make_float2(va.y, va.y);
            *(float2*)&a2[k0 + 2][2 * arow] = make_float2(va.z, va.z);
            *(float2*)&a2[k0 + 3][2 * arow] = make_float2(va.w, va.w);
        }
#pragma unroll
        for (int i_ = 0; i_ < 4; i_++) {
            int f_ = tid + i_ * 256; int r_ = f_ >> 6, q_ = f_ & 63;
            *(float4*)&bsh[r_ * (16 * BPAD) + (q_ >> 2) * BPAD + (q_ & 3) * 4] = rb[i_];
        }
        __syncthreads();
        if (kb + 16 < EMB) { E_LOAD(kb + 16) }

        const float* bp = &bsh[cg * BPAD];
#pragma unroll
        for (int k = 0; k < 16; k++) {
            ulonglong2 aa0 = *(const ulonglong2*)&a2[k][8 * mg];
            ulonglong2 aa1 = *(const ulonglong2*)&a2[k][8 * mg + 4];
            ulonglong2 bb0 = *(const ulonglong2*)(bp + k * (16 * BPAD));
            ulonglong2 bb1 = *(const ulonglong2*)(bp + k * (16 * BPAD) + 4);
            ulonglong2 bb2 = *(const ulonglong2*)(bp + k * (16 * BPAD) + 8);
            ulonglong2 bb3 = *(const ulonglong2*)(bp + k * (16 * BPAD) + 12);
            ull am[4] = { aa0.x, aa0.y, aa1.x, aa1.y };
            ull bq[8] = { bb0.x, bb0.y, bb1.x, bb1.y, bb2.x, bb2.y, bb3.x, bb3.y };
#pragma unroll
            for (int m = 0; m < 4; m++)
#pragma unroll
                for (int q = 0; q < 8; q++) fma2(acc[m * 8 + q], am[m], bq[q]);
        }
    }
#undef E_LOAD

#pragma unroll
    for (int m = 0; m < 4; m++) {
        float* op = g_xproj + (size_t)(by * 64 + mg * 4 + m) * NC + jb + cg * 16;
        float l0, h0, l1, h1;
#pragma unroll
        for (int q = 0; q < 4; q++) {
            up2(acc[m * 8 + 2 * q], l0, h0);
            up2(acc[m * 8 + 2 * q + 1], l1, h1);
            *(float4*)(op + q * 4) = make_float4(l0, h0, l1, h1);
        }
    }
}

// ---------------- kernel 2: PERSISTENT LSTM via mma.sync bf16 3-pass -------------
// 128 CTAs x 512 threads, 1 CTA/SM. CTA: 8 hidden units = N=32 interleaved cols.
// 16 warps = 4 kg (split-K, chunks kg & kg+4) x 4 mt. Warp tile: m16 x n32 x k256.
// wid = kg*4+mt -> SMSP=mt: exactly one active warp per SMSP per chunk window.
// bf16 hi/lo splits, 3 MMA per (k16,n8): AhBh + AlBh + AhBl; fp32 reg accum.
// smem bytes: B persistent [split][32 rows][1024k] bf16        = 131072
//             A stream     [2 bufs][split][64 rows][128k] bf16 = 65536
//             D partials   [4 kg][64 m][34 fp32]               = 34816
#define OFF_A_B  131072
#define OFF_DP   (OFF_A_B + 65536)
#define SMEM_LSTM (OFF_DP + 34816)    // 231424 <= 232448 cap

__global__ __launch_bounds__(512) void k_lstm(float* __restrict__ out)
{
    extern __shared__ __align__(16) float sm[];
    const uint32_t smb = su32(sm);

    int tid  = threadIdx.x;
    int lane = tid & 31, wid = tid >> 5;
    int j0   = blockIdx.x * 8;        // hidden units j0..j0+7
    int C0   = j0 * 4;                // interleaved col base (32 cols)

    // ---- startup: persistent B tiles (W slice bf16 hi/lo), XOR-swizzled ----
#pragma unroll
    for (int i = 0; i < 16; i++) {
        int u = tid + i * 512;        // 0..8191 16B-units
        int s  = u >> 12;
        int rm = u & 4095;
        int c  = rm >> 7;
        int q  = rm & 127;
        int qp = (q & 0x78) | ((q ^ c) & 7);
        *(uint4*)((char*)sm + s * 65536 + c * 2048 + qp * 16) =
            *(const uint4*)&g_WT[s][C0 + c][q * 8];
    }
    __syncthreads();

    // warp tile assignment: wid = kg*4 + mt
    int kg = wid >> 2;                // split-K slice: chunks kg, kg+4
    int mt = wid & 3;                 // m-tile of 16 rows
    int rA = mt * 16 + (lane & 15);   // A ldmatrix row for this lane
    int khalf = lane >> 4;            // 0/1 -> k halves of A x4
    // B x4 lane mapping: cols colB (+16 for second base), k-half qadd
    int colB = (lane & 7) + ((lane >> 4) << 3);
    int qadd = (lane >> 3) & 1;
    uint32_t bB0h = smb + colB * 2048;            // cols 0..15, split hi
    uint32_t bB1h = smb + (16 + colB) * 2048;     // cols 16..31, split hi
    uint32_t bB0l = bB0h + 65536, bB1l = bB1h + 65536;

    // gate-phase mapping: m = tid&63, unit u2 = tid>>6
    int m  = tid & 63;
    int u2 = tid >> 6;
    float c_reg = 0.f;

    // A-chunk loader: chunk = k128; 2048 16B-units / 512 thr = 4 each
#define A_LOAD(BUF, CH, PING) do {                                               \
    _Pragma("unroll")                                                            \
    for (int i_ = 0; i_ < 4; i_++) {                                             \
        int u_ = tid + i_ * 512;                                                 \
        int s_ = u_ >> 10, rm_ = u_ & 1023;                                      \
        int m_ = rm_ >> 4, q_ = rm_ & 15;                                        \
        int qp_ = (q_ & 8) | ((q_ ^ m_) & 7);                                    \
        cpa16(smb + OFF_A_B + (BUF) * 32768 + s_ * 16384 + m_ * 256 + qp_ * 16,  \
              &g_hbf[(PING)][s_][m_][(CH) * 128 + q_ * 8]);                      \
    }                                                                            \
    CP_COMMIT();                                                                 \
} while (0)

    for (int t = 0; t < L_SEQ; t++) {
        const int ping = t & 1, pnext = ping ^ 1;

        // prefetch this step's xproj early (consumed in gate phase)
        float4 xp = *(const float4*)&g_xproj[((size_t)t * 64 + m) * NC + C0 + u2 * 4];

        float d[16];                  // [nt][4]
#pragma unroll
        for (int i = 0; i < 16; i++) d[i] = 0.f;

        A_LOAD(0, 0, ping);
        for (int ch = 0; ch < 8; ch++) {
            int b = ch & 1;
            CP_WAIT0();               // chunk ch resident in buf b
            __syncthreads();          // all warps past chunk ch-1 (buf b^1 free)
            if (ch < 7) A_LOAD(b ^ 1, ch + 1, ping);

            if ((ch & 3) == kg) {     // this warp's chunk (kg or kg+4)
                uint32_t aH = smb + OFF_A_B + b * 32768 + rA * 256;   // split hi
                uint32_t aL = aH + 16384;                              // split lo
                int qbase = ch * 16 + qadd;
#pragma unroll
                for (int ks = 0; ks < 8; ks++) {
                    unsigned ah[4], al[4], bh0[4], bh1[4], bl0[4], bl1[4];
                    int u  = ks * 2 + khalf;
                    int up = (u & 8) | ((u ^ rA) & 7);
                    ldsm_x4(ah, aH + up * 16);
                    ldsm_x4(al, aL + up * 16);
                    int qq = qbase + ks * 2;
                    int qp = (qq & 0x78) | ((qq ^ colB) & 7);  // same for col+16
                    ldsm_x4(bh0, bB0h + qp * 16);
                    ldsm_x4(bh1, bB1h + qp * 16);
                    ldsm_x4(bl0, bB0l + qp * 16);
                    ldsm_x4(bl1, bB1l + qp * 16);
                    mma_bf16(d + 0,  ah, bh0);     mma_bf16(d + 4,  ah, bh0 + 2);
                    mma_bf16(d + 8,  ah, bh1);     mma_bf16(d + 12, ah, bh1 + 2);
                    mma_bf16(d + 0,  al, bh0);     mma_bf16(d + 4,  al, bh0 + 2);
                    mma_bf16(d + 8,  al, bh1);     mma_bf16(d + 12, al, bh1 + 2);
                    mma_bf16(d + 0,  ah, bl0);     mma_bf16(d + 4,  ah, bl0 + 2);
                    mma_bf16(d + 8,  ah, bl1);     mma_bf16(d + 12, ah, bl1 + 2);
                }
            }
        }

        // ---- store split-K partials (dedicated region; stride 34 fp32) ----
        {
            float* DP = (float*)((char*)sm + OFF_DP) + kg * 2176;
            int gid = lane >> 2, tig = lane & 3;
            int r0  = mt * 16 + gid;
#pragma unroll
            for (int nt = 0; nt < 4; nt++) {
                int col = nt * 8 + tig * 2;
                *(float2*)&DP[r0 * 34 + col]       = make_float2(d[nt * 4 + 0],
                                                                 d[nt * 4 + 1]);
                *(float2*)&DP[(r0 + 8) * 34 + col] = make_float2(d[nt * 4 + 2],
                                                                 d[nt * 4 + 3]);
            }
        }
        __syncthreads();

        // ---- gates: thread -> (m, j0+u2); reduce 4 kg slices ----
        {
            const float* DP = (const float*)((const char*)sm + OFF_DP);
            float a0 = xp.x, a1 = xp.y, a2 = xp.z, a3 = xp.w;
#pragma unroll
            for (int g4 = 0; g4 < 4; g4++) {
                const float* p = DP + g4 * 2176 + m * 34 + u2 * 4;
                float2 v0 = *(const float2*)p;
                float2 v1 = *(const float2*)(p + 2);
                a0 += v0.x; a1 += v0.y; a2 += v1.x; a3 += v1.y;
            }
            float cn = sigm_f(a1) * c_reg + sigm_f(a0) * tanh_f(a2);
            c_reg = cn;
            float hv = sigm_f(a3) * tanh_f(cn);

            int j = j0 + u2;
            out[((size_t)t * 64 + m) * 1024 + j] = hv;
            __nv_bfloat16 hh = __float2bfloat16(hv);
            __nv_bfloat16 hl = __float2bfloat16(hv - __bfloat162float(hh));
            g_hbf[pnext][0][m][j] = hh;
            g_hbf[pnext][1][m][j] = hl;
        }

        // ---- software grid barrier (all 128 CTAs resident: 1 CTA/SM) ----
        __syncthreads();
        if (tid == 0) {
            bar_arrive_release(&g_bar);
            unsigned target = (unsigned)(t + 1) * NCTAS;
            while (ld_acquire(&g_bar) < target) { }
        }
        __syncthreads();
    }
#undef A_LOAD
}

// ---------------- launcher ----------------
extern "C" void kernel_launch(void* const* d_in, const int* in_sizes, int n_in,
                              void* d_out, int out_size)
{
    const int*   x   = (const int*)  d_in[0];
    const float* emb = (const float*)d_in[1];
    const float* Wi  = (const float*)d_in[2];
    const float* bi  = (const float*)d_in[3];
    const float* Wf  = (const float*)d_in[4];
    const float* bf  = (const float*)d_in[5];
    const float* Wc  = (const float*)d_in[6];
    const float* bc  = (const float*)d_in[7];
    const float* Wo  = (const float*)d_in[8];
    const float* bo  = (const float*)d_in[9];
    float* out = (float*)d_out;
    (void)in_sizes; (void)n_in; (void)out_size;

    static bool attr_done = false;
    if (!attr_done) {
        cudaFuncSetAttribute(k_lstm, cudaFuncAttributeMaxDynamicSharedMemorySize,
                             SMEM_LSTM);
        attr_done = true;
    }

    k_init<<<256, 256>>>();
    k_reorg<<<((HID + EMB) * HID + 255) / 256, 256>>>(Wi, bi, Wf, bf, Wc, bc, Wo, bo);

    dim3 g1(16, 512);
    k_embed_proj<<<g1, 256>>>(x, emb);

    k_lstm<<<NCTAS, 512, SMEM_LSTM>>>(out);
}

// round 17
// speedup vs baseline: 1.6581x; 1.6581x over previous
#include <cuda_runtime.h>
#include <cuda_bf16.h>
#include <cstdint>

#define L_SEQ 512
#define NB    64
#define HID   1024
#define EMB   512
#define NC    4096   // 4 gates * HID, interleaved col = j*4 + g  (g: 0=i,1=f,2=c,3=o)
#define NCTAS 128    // persistent grid; 1 CTA/SM -> all resident

typedef unsigned long long ull;

// ---------------- device scratch (no allocs allowed) ----------------
__device__ float g_xproj[(size_t)L_SEQ * NB * NC];       // bias + x-part preacts
__device__ float g_Wr[(size_t)(HID + EMB) * NC];         // interleaved fp32 W (embed)
__device__ float g_br[NC];                               // interleaved bias
__device__ __nv_bfloat16 g_WT[2][NC][HID];               // [split][col][k] recurrent W
__device__ __nv_bfloat16 g_hbf[2][2][NB][HID];           // [ping][split][m][k]
__device__ unsigned g_bar;                               // grid barrier counter

// ---------------- packed fp32x2 helpers (embed kernel) ----------------
__device__ __forceinline__ ull pk2(float a, float b) {
    ull r; asm("mov.b64 %0, {%1, %2};" : "=l"(r) : "f"(a), "f"(b)); return r;
}
__device__ __forceinline__ void up2(ull v, float& lo, float& hi) {
    asm("mov.b64 {%0, %1}, %2;" : "=f"(lo), "=f"(hi) : "l"(v));
}
__device__ __forceinline__ void fma2(ull& d, ull a, ull b) {
    asm("fma.rn.f32x2 %0, %1, %2, %0;" : "+l"(d) : "l"(a), "l"(b));
}

// ---------------- misc helpers ----------------
__device__ __forceinline__ uint32_t su32(const void* p) {
    return (uint32_t)__cvta_generic_to_shared(p);
}
__device__ __forceinline__ void cpa16(uint32_t d, const void* g) {
    asm volatile("cp.async.cg.shared.global [%0], [%1], 16;" :: "r"(d), "l"(g));
}
#define CP_COMMIT() asm volatile("cp.async.commit_group;" ::: "memory")
#define CP_WAIT0()  asm volatile("cp.async.wait_group 0;" ::: "memory")

__device__ __forceinline__ void bar_arrive_release(unsigned* p) {
    asm volatile("red.release.gpu.global.add.u32 [%0], %1;" :: "l"(p), "r"(1u)
                 : "memory");
}
__device__ __forceinline__ unsigned ld_acquire(unsigned* p) {
    unsigned v;
    asm volatile("ld.acquire.gpu.global.u32 %0, [%1];" : "=r"(v) : "l"(p) : "memory");
    return v;
}
__device__ __forceinline__ float sigm_f(float v) {
    return __fdividef(1.f, 1.f + __expf(-v));
}
__device__ __forceinline__ float tanh_f(float v) {
    return 1.f - __fdividef(2.f, __expf(2.f * v) + 1.f);
}

// ---------------- tensor-core primitives (portable sm_80 path) ----------------
__device__ __forceinline__ void ldsm_x4(unsigned* r, uint32_t addr) {
    asm volatile("ldmatrix.sync.aligned.m8n8.x4.shared.b16 {%0,%1,%2,%3}, [%4];"
        : "=r"(r[0]), "=r"(r[1]), "=r"(r[2]), "=r"(r[3]) : "r"(addr));
}
__device__ __forceinline__ void mma_bf16(float* d, const unsigned* a,
                                         const unsigned* b) {
    asm volatile(
        "mma.sync.aligned.m16n8k16.row.col.f32.bf16.bf16.f32 "
        "{%0,%1,%2,%3}, {%4,%5,%6,%7}, {%8,%9}, {%0,%1,%2,%3};"
        : "+f"(d[0]), "+f"(d[1]), "+f"(d[2]), "+f"(d[3])
        : "r"(a[0]), "r"(a[1]), "r"(a[2]), "r"(a[3]), "r"(b[0]), "r"(b[1]));
}

// ---------------- init: zero h0 bf16 planes + barrier counter ----------------
__global__ void k_init() {
    int i = blockIdx.x * blockDim.x + threadIdx.x;   // 65536 threads
    unsigned* hb = (unsigned*)g_hbf;                 // 131072 uints total
    hb[i] = 0u; hb[i + 65536] = 0u;
    if (i == 0) g_bar = 0;
}

// ---------------- weight/bias reorg: fp32 interleaved + bf16 hi/lo transposed ----
__global__ void k_reorg(const float* __restrict__ Wi, const float* __restrict__ bi,
                        const float* __restrict__ Wf, const float* __restrict__ bf,
                        const float* __restrict__ Wc, const float* __restrict__ bc,
                        const float* __restrict__ Wo, const float* __restrict__ bo) {
    int idx = blockIdx.x * 256 + threadIdx.x;
    if (idx < (HID + EMB) * HID) {
        int k = idx >> 10, j = idx & (HID - 1);
        size_t s = (size_t)k * HID + j;
        float4 v = make_float4(Wi[s], Wf[s], Wc[s], Wo[s]);
        *(float4*)&g_Wr[(size_t)k * NC + j * 4] = v;
        if (k < HID) {     // recurrent part -> bf16 hi/lo, [col][k]
            float vv[4] = { v.x, v.y, v.z, v.w };
#pragma unroll
            for (int g = 0; g < 4; g++) {
                int col = j * 4 + g;
                __nv_bfloat16 hi = __float2bfloat16(vv[g]);
                __nv_bfloat16 lo = __float2bfloat16(vv[g] - __bfloat162float(hi));
                g_WT[0][col][k] = hi;
                g_WT[1][col][k] = lo;
            }
        }
    }
    if (idx < HID) {
        *(float4*)&g_br[idx * 4] = make_float4(bi[idx], bf[idx], bc[idx], bo[idx]);
    }
}

// ---------------- kernel 1: embedding gather + input projection (unchanged) ------
#define BPAD 20
__global__ __launch_bounds__(256) void k_embed_proj(
    const int* __restrict__ x, const float* __restrict__ emb)
{
    __shared__ float a2[16][132];
    __shared__ float bsh[16 * 16 * BPAD];

    int tid = threadIdx.x;
    int jb  = blockIdx.x * 256;
    int by  = blockIdx.y;

    int arow  = tid & 63;
    int ahalf = tid >> 6;
    long tok  = x[by * 64 + arow];
    const float* erow = emb + (size_t)tok * EMB + ahalf * 4;

    int mg = tid >> 4;
    int cg = tid & 15;

    ull acc[32];
    {
        float4 b0 = *(const float4*)(g_br + jb + cg * 16);
        float4 b1 = *(const float4*)(g_br + jb + cg * 16 + 4);
        float4 b2 = *(const float4*)(g_br + jb + cg * 16 + 8);
        float4 b3 = *(const float4*)(g_br + jb + cg * 16 + 12);
        ull p[8] = { pk2(b0.x, b0.y), pk2(b0.z, b0.w), pk2(b1.x, b1.y), pk2(b1.z, b1.w),
                     pk2(b2.x, b2.y), pk2(b2.z, b2.w), pk2(b3.x, b3.y), pk2(b3.z, b3.w) };
#pragma unroll
        for (int m = 0; m < 4; m++)
#pragma unroll
            for (int q = 0; q < 8; q++) acc[m * 8 + q] = p[q];
    }

    float4 va;
    float4 rb[4];
#define E_LOAD(KB)                                                               \
    va = *(const float4*)(erow + (KB));                                         \
    _Pragma("unroll")                                                            \
    for (int i_ = 0; i_ < 4; i_++) {                                             \
        int f_ = tid + i_ * 256; int r_ = f_ >> 6, q_ = f_ & 63;                 \
        rb[i_] = *(const float4*)&g_Wr[(size_t)(HID + (KB) + r_) * NC + jb + q_ * 4]; \
    }

    E_LOAD(0)

    for (int kb = 0; kb < EMB; kb += 16) {
        __syncthreads();
        {
            int k0 = ahalf * 4;
            *(float2*)&a2[k0 + 0][2 * arow] = make_float2(va.x, va.x);
            *(float2*)&a2[k0 + 1][2 * arow] = make_float2(va.y, va.y);
            *(float2*)&a2[k0 + 2][2 * arow] = make_float2(va.z, va.z);
            *(float2*)&a2[k0 + 3][2 * arow] = make_float2(va.w, va.w);
        }
#pragma unroll
        for (int i_ = 0; i_ < 4; i_++) {
            int f_ = tid + i_ * 256; int r_ = f_ >> 6, q_ = f_ & 63;
            *(float4*)&bsh[r_ * (16 * BPAD) + (q_ >> 2) * BPAD + (q_ & 3) * 4] = rb[i_];
        }
        __syncthreads();
        if (kb + 16 < EMB) { E_LOAD(kb + 16) }

        const float* bp = &bsh[cg * BPAD];
#pragma unroll
        for (int k = 0; k < 16; k++) {
            ulonglong2 aa0 = *(const ulonglong2*)&a2[k][8 * mg];
            ulonglong2 aa1 = *(const ulonglong2*)&a2[k][8 * mg + 4];
            ulonglong2 bb0 = *(const ulonglong2*)(bp + k * (16 * BPAD));
            ulonglong2 bb1 = *(const ulonglong2*)(bp + k * (16 * BPAD) + 4);
            ulonglong2 bb2 = *(const ulonglong2*)(bp + k * (16 * BPAD) + 8);
            ulonglong2 bb3 = *(const ulonglong2*)(bp + k * (16 * BPAD) + 12);
            ull am[4] = { aa0.x, aa0.y, aa1.x, aa1.y };
            ull bq[8] = { bb0.x, bb0.y, bb1.x, bb1.y, bb2.x, bb2.y, bb3.x, bb3.y };
#pragma unroll
            for (int m = 0; m < 4; m++)
#pragma unroll
                for (int q = 0; q < 8; q++) fma2(acc[m * 8 + q], am[m], bq[q]);
        }
    }
#undef E_LOAD

#pragma unroll
    for (int m = 0; m < 4; m++) {
        float* op = g_xproj + (size_t)(by * 64 + mg * 4 + m) * NC + jb + cg * 16;
        float l0, h0, l1, h1;
#pragma unroll
        for (int q = 0; q < 4; q++) {
            up2(acc[m * 8 + 2 * q], l0, h0);
            up2(acc[m * 8 + 2 * q + 1], l1, h1);
            *(float4*)(op + q * 4) = make_float4(l0, h0, l1, h1);
        }
    }
}

// ---------------- kernel 2: PERSISTENT LSTM via mma.sync bf16 3-pass -------------
// 128 CTAs x 512 threads, 1 CTA/SM. CTA: 8 hidden units = N=32 interleaved cols.
// 16 warps = 4 kg x 4 mt; kg splits INSIDE each chunk (warp owns ks = kg*2, kg*2+1
// of the 8 k16-steps) so ALL warps compute in EVERY chunk window (4/SMSP).
// Warp tile: m16 x n32 x k32-per-chunk. A frags loaded once; B 4x (over mt).
// bf16 hi/lo splits, 3 MMA per (k16,n8): AhBh + AlBh + AhBl; fp32 reg accum;
// 4-way split-K reduce via smem at the end of each step.
// smem bytes: B persistent [split][32 rows][1024k] bf16        = 131072
//             A stream     [2 bufs][split][64 rows][128k] bf16 = 65536
//             D partials   [4 kg][64 m][34 fp32]               = 34816
#define OFF_A_B  131072
#define OFF_DP   (OFF_A_B + 65536)
#define SMEM_LSTM (OFF_DP + 34816)    // 231424 <= 232448 cap

__global__ __launch_bounds__(512) void k_lstm(float* __restrict__ out)
{
    extern __shared__ __align__(16) float sm[];
    const uint32_t smb = su32(sm);

    int tid  = threadIdx.x;
    int lane = tid & 31, wid = tid >> 5;
    int j0   = blockIdx.x * 8;        // hidden units j0..j0+7
    int C0   = j0 * 4;                // interleaved col base (32 cols)

    // ---- startup: persistent B tiles (W slice bf16 hi/lo), XOR-swizzled ----
#pragma unroll
    for (int i = 0; i < 16; i++) {
        int u = tid + i * 512;        // 0..8191 16B-units
        int s  = u >> 12;
        int rm = u & 4095;
        int c  = rm >> 7;
        int q  = rm & 127;
        int qp = (q & 0x78) | ((q ^ c) & 7);
        *(uint4*)((char*)sm + s * 65536 + c * 2048 + qp * 16) =
            *(const uint4*)&g_WT[s][C0 + c][q * 8];
    }
    __syncthreads();

    // warp tile assignment: wid = kg*4 + mt  (SMSP = mt -> 4 warps/SMSP active)
    int kg = wid >> 2;                // in-chunk k-slice: ks = kg*2, kg*2+1
    int mt = wid & 3;                 // m-tile of 16 rows
    int rA = mt * 16 + (lane & 15);   // A ldmatrix row for this lane
    int khalf = lane >> 4;            // 0/1 -> k halves of A x4
    // B x4 lane mapping: cols colB (+16 for second base), k-half qadd
    int colB = (lane & 7) + ((lane >> 4) << 3);
    int qadd = (lane >> 3) & 1;
    uint32_t bB0h = smb + colB * 2048;            // cols 0..15, split hi
    uint32_t bB1h = smb + (16 + colB) * 2048;     // cols 16..31, split hi
    uint32_t bB0l = bB0h + 65536, bB1l = bB1h + 65536;

    // gate-phase mapping: m = tid&63, unit u2 = tid>>6
    int m  = tid & 63;
    int u2 = tid >> 6;
    float c_reg = 0.f;

    // A-chunk loader: chunk = k128; 2048 16B-units / 512 thr = 4 each
#define A_LOAD(BUF, CH, PING) do {                                               \
    _Pragma("unroll")                                                            \
    for (int i_ = 0; i_ < 4; i_++) {                                             \
        int u_ = tid + i_ * 512;                                                 \
        int s_ = u_ >> 10, rm_ = u_ & 1023;                                      \
        int m_ = rm_ >> 4, q_ = rm_ & 15;                                        \
        int qp_ = (q_ & 8) | ((q_ ^ m_) & 7);                                    \
        cpa16(smb + OFF_A_B + (BUF) * 32768 + s_ * 16384 + m_ * 256 + qp_ * 16,  \
              &g_hbf[(PING)][s_][m_][(CH) * 128 + q_ * 8]);                      \
    }                                                                            \
    CP_COMMIT();                                                                 \
} while (0)

    for (int t = 0; t < L_SEQ; t++) {
        const int ping = t & 1, pnext = ping ^ 1;

        // prefetch this step's xproj early (consumed in gate phase)
        float4 xp = *(const float4*)&g_xproj[((size_t)t * 64 + m) * NC + C0 + u2 * 4];

        float d[16];                  // [nt][4]
#pragma unroll
        for (int i = 0; i < 16; i++) d[i] = 0.f;

        A_LOAD(0, 0, ping);
        for (int ch = 0; ch < 8; ch++) {
            int b = ch & 1;
            CP_WAIT0();               // chunk ch resident in buf b
            __syncthreads();          // all warps past chunk ch-1 (buf b^1 free)
            if (ch < 7) A_LOAD(b ^ 1, ch + 1, ping);

            uint32_t aH = smb + OFF_A_B + b * 32768 + rA * 256;   // split hi
            uint32_t aL = aH + 16384;                              // split lo
#pragma unroll
            for (int s = 0; s < 2; s++) {
                int ks = kg * 2 + s;              // this warp's k16-steps
                unsigned ah[4], al[4], bh0[4], bh1[4], bl0[4], bl1[4];
                int u  = ks * 2 + khalf;
                int up = (u & 8) | ((u ^ rA) & 7);
                ldsm_x4(ah, aH + up * 16);
                ldsm_x4(al, aL + up * 16);
                int qq = (ch * 8 + ks) * 2 + qadd;
                int qp = (qq & 0x78) | ((qq ^ colB) & 7);  // same for col+16
                ldsm_x4(bh0, bB0h + qp * 16);
                ldsm_x4(bh1, bB1h + qp * 16);
                ldsm_x4(bl0, bB0l + qp * 16);
                ldsm_x4(bl1, bB1l + qp * 16);
                mma_bf16(d + 0,  ah, bh0);     mma_bf16(d + 4,  ah, bh0 + 2);
                mma_bf16(d + 8,  ah, bh1);     mma_bf16(d + 12, ah, bh1 + 2);
                mma_bf16(d + 0,  al, bh0);     mma_bf16(d + 4,  al, bh0 + 2);
                mma_bf16(d + 8,  al, bh1);     mma_bf16(d + 12, al, bh1 + 2);
                mma_bf16(d + 0,  ah, bl0);     mma_bf16(d + 4,  ah, bl0 + 2);
                mma_bf16(d + 8,  ah, bl1);     mma_bf16(d + 12, ah, bl1 + 2);
            }
        }

        // ---- store split-K partials (dedicated region; stride 34 fp32) ----
        {
            float* DP = (float*)((char*)sm + OFF_DP) + kg * 2176;
            int gid = lane >> 2, tig = lane & 3;
            int r0  = mt * 16 + gid;
#pragma unroll
            for (int nt = 0; nt < 4; nt++) {
                int col = nt * 8 + tig * 2;
                *(float2*)&DP[r0 * 34 + col]       = make_float2(d[nt * 4 + 0],
                                                                 d[nt * 4 + 1]);
                *(float2*)&DP[(r0 + 8) * 34 + col] = make_float2(d[nt * 4 + 2],
                                                                 d[nt * 4 + 3]);
            }
        }
        __syncthreads();

        // ---- gates: thread -> (m, j0+u2); reduce 4 kg slices ----
        {
            const float* DP = (const float*)((const char*)sm + OFF_DP);
            float a0 = xp.x, a1 = xp.y, a2 = xp.z, a3 = xp.w;
#pragma unroll
            for (int g4 = 0; g4 < 4; g4++) {
                const float* p = DP + g4 * 2176 + m * 34 + u2 * 4;
                float2 v0 = *(const float2*)p;
                float2 v1 = *(const float2*)(p + 2);
                a0 += v0.x; a1 += v0.y; a2 += v1.x; a3 += v1.y;
            }
            float cn = sigm_f(a1) * c_reg + sigm_f(a0) * tanh_f(a2);
            c_reg = cn;
            float hv = sigm_f(a3) * tanh_f(cn);

            int j = j0 + u2;
            out[((size_t)t * 64 + m) * 1024 + j] = hv;
            __nv_bfloat16 hh = __float2bfloat16(hv);
            __nv_bfloat16 hl = __float2bfloat16(hv - __bfloat162float(hh));
            g_hbf[pnext][0][m][j] = hh;
            g_hbf[pnext][1][m][j] = hl;
        }

        // ---- software grid barrier (all 128 CTAs resident: 1 CTA/SM) ----
        __syncthreads();
        if (tid == 0) {
            bar_arrive_release(&g_bar);
            unsigned target = (unsigned)(t + 1) * NCTAS;
            while (ld_acquire(&g_bar) < target) { }
        }
        __syncthreads();
    }
#undef A_LOAD
}

// ---------------- launcher ----------------
extern "C" void kernel_launch(void* const* d_in, const int* in_sizes, int n_in,
                              void* d_out, int out_size)
{
    const int*   x   = (const int*)  d_in[0];
    const float* emb = (const float*)d_in[1];
    const float* Wi  = (const float*)d_in[2];
    const float* bi  = (const float*)d_in[3];
    const float* Wf  = (const float*)d_in[4];
    const float* bf  = (const float*)d_in[5];
    const float* Wc  = (const float*)d_in[6];
    const float* bc  = (const float*)d_in[7];
    const float* Wo  = (const float*)d_in[8];
    const float* bo  = (const float*)d_in[9];
    float* out = (float*)d_out;
    (void)in_sizes; (void)n_in; (void)out_size;

    static bool attr_done = false;
    if (!attr_done) {
        cudaFuncSetAttribute(k_lstm, cudaFuncAttributeMaxDynamicSharedMemorySize,
                             SMEM_LSTM);
        attr_done = true;
    }

    k_init<<<256, 256>>>();
    k_reorg<<<((HID + EMB) * HID + 255) / 256, 256>>>(Wi, bi, Wf, bf, Wc, bc, Wo, bo);

    dim3 g1(16, 512);
    k_embed_proj<<<g1, 256>>>(x, emb);

    k_lstm<<<NCTAS, 512, SMEM_LSTM>>>(out);
}